// round 7
// baseline (speedup 1.0000x reference)
#include <cuda_runtime.h>
#include <cuda_bf16.h>
#include <cstdint>

// Problem constants (LengthRegulator_42691974922415):
//   pred_duration:           [B=32, L=512] int32, values in [0, 8)
//   phoneme_hidden_sequence: [B=32, L=512, D=384] float32
//   output:                  [B=32, T=L*7=3584, D=384] float32
static constexpr int B  = 32;
static constexpr int L  = 512;
static constexpr int D  = 384;
static constexpr int T  = 3584;            // L * (DUR_MAX-1)
static constexpr int FRAME_BYTES = D * 4;  // 1536 B per frame row
static constexpr int TOTAL_FRAMES = B * T; // 114688

// Frames staged per block (output of one block is one contiguous 43 KB span).
static constexpr int FPB  = 28;
static constexpr int NBLK = TOTAL_FRAMES / FPB;          // 4096 (exact)
static constexpr int STAGE_BYTES = FPB * FRAME_BYTES;    // 43008

// Scratch: frame -> source hidden-row id (b*L + l), or -1 for zero frames.
__device__ int g_frame_idx[TOTAL_FRAMES];

// ---------------------------------------------------------------------------
// Kernel 1: per-batch duration scan + frame-index scatter (unchanged; ~2 us).
// ---------------------------------------------------------------------------
__global__ void __launch_bounds__(L) build_index_kernel(const int* __restrict__ dur)
{
    const int b    = blockIdx.x;
    const int tid  = threadIdx.x;          // phoneme index l
    const int lane = tid & 31;
    const int w    = tid >> 5;             // warp id, 0..15

    int d = dur[b * L + tid];

    int x = d;
    #pragma unroll
    for (int o = 1; o < 32; o <<= 1) {
        int y = __shfl_up_sync(0xffffffffu, x, o);
        if (lane >= o) x += y;
    }

    __shared__ int wsum[16];
    if (lane == 31) wsum[w] = x;
    __syncthreads();

    if (w == 0) {
        int s = (lane < 16) ? wsum[lane] : 0;
        #pragma unroll
        for (int o = 1; o < 16; o <<= 1) {
            int y = __shfl_up_sync(0xffffffffu, s, o);
            if (lane >= o) s += y;
        }
        if (lane < 16) wsum[lane] = s;
    }
    __syncthreads();

    const int incl  = x + (w > 0 ? wsum[w - 1] : 0);
    const int start = incl - d;

    int* fi = g_frame_idx + b * T;
    #pragma unroll
    for (int t = tid; t < T; t += L) fi[t] = -1;
    __syncthreads();

    const int src = b * L + tid;
    for (int k = 0; k < d; ++k)            // d <= 7
        fi[start + k] = src;
}

// ---------------------------------------------------------------------------
// Kernel 2: TMA bulk-copy expand. Round 4-6 showed the per-thread LDG/STG
// path is LSU-issue-bound (~21 cyc of issue cost per 16 B element; plateau
// 32 us across all ILP/occupancy configs). Here the SM issues almost no LSU
// work: per block, <=28 cp.async.bulk loads (1536 B each, gathered rows),
// STS zero-fill for zero frames, then ONE 43 KB cp.async.bulk store of the
// contiguous output span. Data moves on the async engines.
// ---------------------------------------------------------------------------
__global__ void __launch_bounds__(128) expand_tma_kernel(const char* __restrict__ hid,
                                                         char* __restrict__ out)
{
    __shared__ __align__(8) uint64_t s_mbar;
    __shared__ int s_idx[FPB];
    extern __shared__ __align__(16) char s_stage[];

    const int tid = threadIdx.x;

    uint32_t mbar_u32, stage_u32;
    asm("{ .reg .u64 t; cvta.to.shared.u64 t, %1; cvt.u32.u64 %0, t; }"
        : "=r"(mbar_u32) : "l"(&s_mbar));
    asm("{ .reg .u64 t; cvta.to.shared.u64 t, %1; cvt.u32.u64 %0, t; }"
        : "=r"(stage_u32) : "l"(s_stage));

    const int f0 = blockIdx.x * FPB;

    // Load this block's frame indices; thread tid handles frame tid (tid<FPB).
    int my = -1;
    if (tid < FPB) {
        my = __ldg(&g_frame_idx[f0 + tid]);
        s_idx[tid] = my;
    }

    if (tid == 0)
        asm volatile("mbarrier.init.shared.b64 [%0], 1;" :: "r"(mbar_u32) : "memory");

    // Barrier + count of frames that need a gather load (zero frames excluded).
    const int n_loads = __syncthreads_count(my >= 0);

    if (tid == 0)
        asm volatile("mbarrier.arrive.expect_tx.shared.b64 _, [%0], %1;"
                     :: "r"(mbar_u32), "r"((uint32_t)(n_loads * FRAME_BYTES))
                     : "memory");
    __syncthreads();   // expect_tx visible before any complete_tx can land

    // Issue one 1536 B bulk gather per nonzero frame.
    if (tid < FPB && my >= 0) {
        const uint32_t dst = stage_u32 + tid * FRAME_BYTES;
        const char*    src = hid + (size_t)my * FRAME_BYTES;
        asm volatile(
            "cp.async.bulk.shared::cta.global.mbarrier::complete_tx::bytes "
            "[%0], [%1], %2, [%3];"
            :: "r"(dst), "l"(src), "r"((uint32_t)FRAME_BYTES), "r"(mbar_u32)
            : "memory");
    }

    // Zero-fill slots of zero frames (threads 0..95 write one float4 each).
    {
        const int off = tid * 16;
        const float4 z = make_float4(0.f, 0.f, 0.f, 0.f);
        if (off < FRAME_BYTES) {
            for (int f = 0; f < FPB; ++f) {
                if (s_idx[f] < 0)
                    *reinterpret_cast<float4*>(s_stage + f * FRAME_BYTES + off) = z;
            }
        }
    }

    // Wait for all gather loads to land.
    {
        uint32_t done;
        asm volatile(
            "{\n\t.reg .pred p;\n\t"
            "mbarrier.try_wait.parity.acquire.cta.shared::cta.b64 p, [%1], 0;\n\t"
            "selp.b32 %0, 1, 0, p;\n\t}"
            : "=r"(done) : "r"(mbar_u32) : "memory");
        while (!done) {
            asm volatile(
                "{\n\t.reg .pred p;\n\t"
                "mbarrier.try_wait.parity.acquire.cta.shared::cta.b64 p, [%1], 0, 0x989680;\n\t"
                "selp.b32 %0, 1, 0, p;\n\t}"
                : "=r"(done) : "r"(mbar_u32) : "memory");
        }
    }
    __syncthreads();                                   // zero-fill STS done
    asm volatile("fence.proxy.async.shared::cta;" ::: "memory");

    // One bulk store of the whole contiguous 43 KB output span.
    if (tid == 0) {
        char* dst = out + (size_t)f0 * FRAME_BYTES;
        asm volatile(
            "cp.async.bulk.global.shared::cta.bulk_group [%0], [%1], %2;"
            :: "l"(dst), "r"(stage_u32), "r"((uint32_t)STAGE_BYTES)
            : "memory");
        asm volatile("cp.async.bulk.commit_group;" ::: "memory");
        asm volatile("cp.async.bulk.wait_group 0;" ::: "memory");
        asm volatile("mbarrier.inval.shared.b64 [%0];" :: "r"(mbar_u32) : "memory");
    }
}

// ---------------------------------------------------------------------------
extern "C" void kernel_launch(void* const* d_in, const int* in_sizes, int n_in,
                              void* d_out, int out_size)
{
    const int*  dur = (const int*)d_in[0];     // [B, L] int32
    const char* hid = (const char*)d_in[1];    // [B, L, D] f32 bytes
    char*       out = (char*)d_out;            // [B, T, D] f32 bytes

    static bool attr_set = false;
    if (!attr_set) {
        cudaFuncSetAttribute(expand_tma_kernel,
                             cudaFuncAttributeMaxDynamicSharedMemorySize,
                             STAGE_BYTES);
        attr_set = true;
    }

    build_index_kernel<<<B, L>>>(dur);
    expand_tma_kernel<<<NBLK, 128, STAGE_BYTES>>>(hid, out);
}

// round 8
// speedup vs baseline: 1.1727x; 1.1727x over previous
#include <cuda_runtime.h>
#include <cuda_bf16.h>
#include <cstdint>

// Problem constants (LengthRegulator_42691974922415):
//   pred_duration:           [B=32, L=512] int32, values in [0, 8)
//   phoneme_hidden_sequence: [B=32, L=512, D=384] float32
//   output:                  [B=32, T=L*7=3584, D=384] float32
static constexpr int B  = 32;
static constexpr int L  = 512;
static constexpr int D  = 384;
static constexpr int T  = 3584;       // L * (DUR_MAX-1)
static constexpr int D4 = D / 4;      // 96 float4 per row
static constexpr int TOTAL_ROWS = B * T;   // 114688

// Scratch: frame -> source hidden-row id (b*L + l), or -1 for zero frames.
__device__ int g_frame_idx[TOTAL_ROWS];

// ---------------------------------------------------------------------------
// Kernel 1: per-batch duration scan + frame-index scatter (unchanged; ~2 us).
// ---------------------------------------------------------------------------
__global__ void __launch_bounds__(L) build_index_kernel(const int* __restrict__ dur)
{
    const int b    = blockIdx.x;
    const int tid  = threadIdx.x;          // phoneme index l
    const int lane = tid & 31;
    const int w    = tid >> 5;             // warp id, 0..15

    int d = dur[b * L + tid];

    int x = d;
    #pragma unroll
    for (int o = 1; o < 32; o <<= 1) {
        int y = __shfl_up_sync(0xffffffffu, x, o);
        if (lane >= o) x += y;
    }

    __shared__ int wsum[16];
    if (lane == 31) wsum[w] = x;
    __syncthreads();

    if (w == 0) {
        int s = (lane < 16) ? wsum[lane] : 0;
        #pragma unroll
        for (int o = 1; o < 16; o <<= 1) {
            int y = __shfl_up_sync(0xffffffffu, s, o);
            if (lane >= o) s += y;
        }
        if (lane < 16) wsum[lane] = s;
    }
    __syncthreads();

    const int incl  = x + (w > 0 ? wsum[w - 1] : 0);
    const int start = incl - d;

    int* fi = g_frame_idx + b * T;
    #pragma unroll
    for (int t = tid; t < T; t += L) fi[t] = -1;
    __syncthreads();

    const int src = b * L + tid;
    for (int k = 0; k < d; ++k)            // d <= 7
        fi[start + k] = src;
}

// ---------------------------------------------------------------------------
// Kernel 2: warp-per-row expand.
// Rounds 4-7 showed the plateau is LSU-issue cost (~24 cyc per 16 B element:
// idx LDG + LDG.128 + STG.128), identical across ILP and TMA variants.
// This layout cuts LSU work two ways:
//   * idx is loaded ONCE per 96-element row (warp-broadcast), not per element;
//   * zero rows (~50%) take a warp-UNIFORM branch that skips the gather
//     loads entirely (predicated-off LDGs previously still paid issue cost).
// Each warp owns 4 consecutive rows; all gathers are issued before any store
// (MLP up to 12 in-flight LDG.128 per thread). Stores stay .cs to keep the
// 25 MB hidden tensor resident in L2 under the 176 MB output stream.
//   grid: 114688 rows / (8 warps * 4 rows) = 3584 blocks of 256 threads.
// ---------------------------------------------------------------------------
static constexpr int RPW = 4;   // rows per warp
static constexpr int WPB = 8;   // warps per block (256 threads)

__global__ void __launch_bounds__(256, 2) expand_kernel(const float4* __restrict__ hid,
                                                        float4* __restrict__ out)
{
    const int warp  = blockIdx.x * WPB + (threadIdx.x >> 5);
    const int lane  = threadIdx.x & 31;
    const int row0  = warp * RPW;

    // One idx load per row; same address across the warp -> L1 broadcast.
    int idx[RPW];
    #pragma unroll
    for (int r = 0; r < RPW; ++r)
        idx[r] = __ldg(&g_frame_idx[row0 + r]);

    // Gather phase: warp-uniform branch per row; zero rows issue no loads.
    float4 v[RPW][3];
    #pragma unroll
    for (int r = 0; r < RPW; ++r) {
        if (idx[r] >= 0) {
            const float4* src = hid + idx[r] * D4 + lane;
            #pragma unroll
            for (int p = 0; p < 3; ++p)
                v[r][p] = __ldg(src + p * 32);
        } else {
            #pragma unroll
            for (int p = 0; p < 3; ++p)
                v[r][p] = make_float4(0.f, 0.f, 0.f, 0.f);
        }
    }

    // Store phase: 12 coalesced 512 B warp-stores, streaming policy.
    #pragma unroll
    for (int r = 0; r < RPW; ++r) {
        float4* dst = out + (size_t)(row0 + r) * D4 + lane;
        #pragma unroll
        for (int p = 0; p < 3; ++p)
            __stcs(dst + p * 32, v[r][p]);
    }
}

// ---------------------------------------------------------------------------
extern "C" void kernel_launch(void* const* d_in, const int* in_sizes, int n_in,
                              void* d_out, int out_size)
{
    const int*    dur = (const int*)d_in[0];      // [B, L] int32
    const float4* hid = (const float4*)d_in[1];   // [B, L, D] f32 as float4
    float4*       out = (float4*)d_out;           // [B, T, D] f32 as float4

    build_index_kernel<<<B, L>>>(dur);

    const int nblk = TOTAL_ROWS / (WPB * RPW);    // 3584
    expand_kernel<<<nblk, 256>>>(hid, out);
}